// round 11
// baseline (speedup 1.0000x reference)
#include <cuda_runtime.h>
#include <cuda_fp16.h>
#include <cstdint>

#define BATCH   2
#define SEQ     2048
#define DIM     2048
#define NHEADS  32
#define NKVH    8
#define HD      64
#define QKVROW  3072
#define MROWS   4096

// ---------------- scratch (__device__ globals; no allocs) ------------------
__device__ __half g_xh  [(size_t)MROWS  * DIM];
__device__ __half g_wqh [(size_t)QKVROW * DIM];
__device__ __half g_woh [(size_t)DIM    * DIM];
__device__ __half g_qkvh[(size_t)MROWS  * QKVROW];
__device__ __half g_atth[(size_t)MROWS  * DIM];

// ---------------- helpers ---------------------------------------------------
__device__ __forceinline__ uint32_t smem_u32(const void* p) {
    uint32_t a;
    asm("{ .reg .u64 t; cvta.to.shared.u64 t, %1; cvt.u32.u64 %0, t; }" : "=r"(a) : "l"(p));
    return a;
}
#define SWZ128(off) ((off) ^ (((off) >> 3) & 0x70))

__device__ __forceinline__ void cp16(uint32_t dst, const void* src) {
    asm volatile("cp.async.cg.shared.global [%0], [%1], 16;" :: "r"(dst), "l"(src) : "memory");
}
__device__ __forceinline__ void cp_commit() {
    asm volatile("cp.async.commit_group;" ::: "memory");
}
template <int N>
__device__ __forceinline__ void cp_wait() {
    asm volatile("cp.async.wait_group %0;" :: "n"(N) : "memory");
}
__device__ __forceinline__ void ldsm4(uint32_t* r, uint32_t addr) {
    asm volatile("ldmatrix.sync.aligned.m8n8.x4.shared.b16 {%0,%1,%2,%3}, [%4];"
                 : "=r"(r[0]), "=r"(r[1]), "=r"(r[2]), "=r"(r[3]) : "r"(addr));
}
__device__ __forceinline__ void ldsm4t(uint32_t* r, uint32_t addr) {
    asm volatile("ldmatrix.sync.aligned.m8n8.x4.trans.shared.b16 {%0,%1,%2,%3}, [%4];"
                 : "=r"(r[0]), "=r"(r[1]), "=r"(r[2]), "=r"(r[3]) : "r"(addr));
}
__device__ __forceinline__ void mma16816(float* c, const uint32_t* a, const uint32_t* b) {
    asm volatile("mma.sync.aligned.m16n8k16.row.col.f32.f16.f16.f32 "
                 "{%0,%1,%2,%3}, {%4,%5,%6,%7}, {%8,%9}, {%0,%1,%2,%3};"
                 : "+f"(c[0]), "+f"(c[1]), "+f"(c[2]), "+f"(c[3])
                 : "r"(a[0]), "r"(a[1]), "r"(a[2]), "r"(a[3]), "r"(b[0]), "r"(b[1]));
}

// ---------------------------------------------------------------------------
// fused fp32 -> fp16 conversion for x, Wqkv, Wout in ONE launch
// ---------------------------------------------------------------------------
#define N1 (MROWS * DIM)
#define N2 (QKVROW * DIM)
#define N3 (DIM * DIM)
#define CONV_BLOCKS ((N1 + N2 + N3) / 2048)

__global__ void to_half3(const float* __restrict__ x,  __half* __restrict__ xh,
                         const float* __restrict__ wq, __half* __restrict__ wqh,
                         const float* __restrict__ wo, __half* __restrict__ woh)
{
    const float* in;
    __half* out;
    int bid = blockIdx.x;
    if (bid < N1 / 2048)            { in = x;  out = xh; }
    else if (bid < (N1 + N2) / 2048){ in = wq; out = wqh; bid -= N1 / 2048; }
    else                            { in = wo; out = woh; bid -= (N1 + N2) / 2048; }

    int i = (bid * 256 + threadIdx.x) * 8;
    float4 a = *(const float4*)(in + i);
    float4 b = *(const float4*)(in + i + 4);
    __half2* o = (__half2*)(out + i);
    o[0] = __floats2half2_rn(a.x, a.y);
    o[1] = __floats2half2_rn(a.z, a.w);
    o[2] = __floats2half2_rn(b.x, b.y);
    o[3] = __floats2half2_rn(b.z, b.w);
}

// ---------------------------------------------------------------------------
// HMMA GEMM v1 (round-7 form, frozen — used for GEMM2):
// BM=BN=128, BK=64, 4 warps 64x64, 3 stages, 2 blocks/SM.
// ---------------------------------------------------------------------------
#define GBK   64
#define ASZ   (128 * 128)
#define GSTG_B (2 * ASZ)
#define GEMM_SMEM (3 * GSTG_B)

template<bool HALF_OUT>
__global__ __launch_bounds__(128, 2)
void gemm_h(const __half* __restrict__ A, const __half* __restrict__ B,
            void* __restrict__ Cv, int M, int N, int K)
{
    extern __shared__ char smem[];
    const uint32_t sb0 = smem_u32(smem);
    const int tid = threadIdx.x, lane = tid & 31, wid = tid >> 5;
    const int wm = wid & 1, wn = wid >> 1;
    const int row0 = blockIdx.y * 128, col0 = blockIdx.x * 128;
    const int NITER = K / GBK;

    auto load_stage = [&](int s, int c) {
        const int k0 = c * GBK;
        const uint32_t sA = sb0 + s * GSTG_B, sB = sA + ASZ;
#pragma unroll
        for (int t = 0; t < 8; t++) {
            int idx = tid + t * 128;
            int r = idx >> 3, cc = idx & 7;
            uint32_t off = SWZ128((uint32_t)(r * 128 + cc * 16));
            cp16(sA + off, A + (size_t)(row0 + r) * K + k0 + cc * 8);
            cp16(sB + off, B + (size_t)(col0 + r) * K + k0 + cc * 8);
        }
        cp_commit();
    };

    float acc[4][8][4];
#pragma unroll
    for (int a = 0; a < 4; a++)
#pragma unroll
        for (int b = 0; b < 8; b++)
#pragma unroll
            for (int c = 0; c < 4; c++) acc[a][b][c] = 0.f;

    load_stage(0, 0);
    load_stage(1, 1);

    for (int i = 0; i < NITER; i++) {
        if (i + 1 < NITER) cp_wait<1>(); else cp_wait<0>();
        __syncthreads();
        if (i + 2 < NITER) load_stage((i + 2) % 3, i + 2);

        const uint32_t sA = sb0 + (i % 3) * GSTG_B, sB = sA + ASZ;
#pragma unroll
        for (int ks = 0; ks < 4; ks++) {
            uint32_t af[4][4];
#pragma unroll
            for (int mt = 0; mt < 4; mt++)
                ldsm4(af[mt], sA + SWZ128((uint32_t)((wm * 64 + mt * 16 + (lane & 15)) * 128
                                                      + (ks * 2 + (lane >> 4)) * 16)));
#pragma unroll
            for (int bt = 0; bt < 4; bt++) {
                uint32_t bf[4];
                ldsm4(bf, sB + SWZ128((uint32_t)((wn * 64 + bt * 16 + ((lane >> 4) << 3) + (lane & 7)) * 128
                                                  + (ks * 2 + ((lane >> 3) & 1)) * 16)));
#pragma unroll
                for (int mt = 0; mt < 4; mt++) {
                    mma16816(acc[mt][2 * bt],     af[mt], bf);
                    mma16816(acc[mt][2 * bt + 1], af[mt], bf + 2);
                }
            }
        }
    }

#pragma unroll
    for (int mt = 0; mt < 4; mt++) {
#pragma unroll
        for (int nt = 0; nt < 8; nt++) {
            const int col = col0 + wn * 64 + nt * 8 + (lane & 3) * 2;
            const int r0  = row0 + wm * 64 + mt * 16 + (lane >> 2);
            if (HALF_OUT) {
                __half* C = (__half*)Cv;
                *(__half2*)(C + (size_t)r0 * N + col)       = __floats2half2_rn(acc[mt][nt][0], acc[mt][nt][1]);
                *(__half2*)(C + (size_t)(r0 + 8) * N + col) = __floats2half2_rn(acc[mt][nt][2], acc[mt][nt][3]);
            } else {
                float* C = (float*)Cv;
                *(float2*)(C + (size_t)r0 * N + col)       = make_float2(acc[mt][nt][0], acc[mt][nt][1]);
                *(float2*)(C + (size_t)(r0 + 8) * N + col) = make_float2(acc[mt][nt][2], acc[mt][nt][3]);
            }
        }
    }
}

// ---------------------------------------------------------------------------
// HMMA GEMM v2 (experimental — GEMM1): BM=128, BN=256, BK=64, 256 threads,
// 8 warps 64x64 (wm = wid&1, wn = wid>>1), 4 smem stages (2-tile prefetch,
// cp_wait<2>), ks-stagger between SMSP-sharing warps. 1 block/SM.
// ---------------------------------------------------------------------------
#define V2_ASZ   (128 * 128)                 // 16384 B
#define V2_BSZ   (256 * 128)                 // 32768 B
#define V2_STG   (V2_ASZ + V2_BSZ)           // 49152 B
#define GEMM2_SMEM (4 * V2_STG)              // 196608 B

template<bool HALF_OUT>
__global__ __launch_bounds__(256, 1)
void gemm_h2(const __half* __restrict__ A, const __half* __restrict__ B,
             void* __restrict__ Cv, int M, int N, int K)
{
    extern __shared__ char smem[];
    const uint32_t sb0 = smem_u32(smem);
    const int tid = threadIdx.x, lane = tid & 31, wid = tid >> 5;
    const int wm = wid & 1, wn = wid >> 1;          // wn 0..3
    const int ksrot = ((wid >> 2) & 1) * 2;         // stagger warps sharing an SMSP
    const int row0 = blockIdx.y * 128, col0 = blockIdx.x * 256;
    const int NITER = K / GBK;

    auto load_stage = [&](int s, int c) {
        const int k0 = c * GBK;
        const uint32_t sA = sb0 + s * V2_STG, sB = sA + V2_ASZ;
#pragma unroll
        for (int t = 0; t < 4; t++) {               // A: 1024 chunks / 256 thr
            int idx = tid + t * 256;
            int r = idx >> 3, cc = idx & 7;
            uint32_t off = SWZ128((uint32_t)(r * 128 + cc * 16));
            cp16(sA + off, A + (size_t)(row0 + r) * K + k0 + cc * 8);
        }
#pragma unroll
        for (int t = 0; t < 8; t++) {               // B: 2048 chunks / 256 thr
            int idx = tid + t * 256;
            int r = idx >> 3, cc = idx & 7;
            uint32_t off = SWZ128((uint32_t)(r * 128 + cc * 16));
            cp16(sB + off, B + (size_t)(col0 + r) * K + k0 + cc * 8);
        }
        cp_commit();
    };

    float acc[4][8][4];
#pragma unroll
    for (int a = 0; a < 4; a++)
#pragma unroll
        for (int b = 0; b < 8; b++)
#pragma unroll
            for (int c = 0; c < 4; c++) acc[a][b][c] = 0.f;

    load_stage(0, 0);
    load_stage(1, 1);
    load_stage(2, 2);

    for (int i = 0; i < NITER; i++) {
        if (i + 2 < NITER) cp_wait<2>();
        else if (i + 1 < NITER) cp_wait<1>();
        else cp_wait<0>();
        __syncthreads();
        if (i + 3 < NITER) load_stage((i + 3) & 3, i + 3);

        const uint32_t sA = sb0 + (i & 3) * V2_STG, sB = sA + V2_ASZ;
#pragma unroll
        for (int kk = 0; kk < 4; kk++) {
            const int ks = (kk + ksrot) & 3;
            uint32_t af[4][4];
#pragma unroll
            for (int mt = 0; mt < 4; mt++)
                ldsm4(af[mt], sA + SWZ128((uint32_t)((wm * 64 + mt * 16 + (lane & 15)) * 128
                                                      + (ks * 2 + (lane >> 4)) * 16)));
#pragma unroll
            for (int bt = 0; bt < 4; bt++) {
                uint32_t bf[4];
                ldsm4(bf, sB + SWZ128((uint32_t)((wn * 64 + bt * 16 + ((lane >> 4) << 3) + (lane & 7)) * 128
                                                  + (ks * 2 + ((lane >> 3) & 1)) * 16)));
#pragma unroll
                for (int mt = 0; mt < 4; mt++) {
                    mma16816(acc[mt][2 * bt],     af[mt], bf);
                    mma16816(acc[mt][2 * bt + 1], af[mt], bf + 2);
                }
            }
        }
    }

#pragma unroll
    for (int mt = 0; mt < 4; mt++) {
#pragma unroll
        for (int nt = 0; nt < 8; nt++) {
            const int col = col0 + wn * 64 + nt * 8 + (lane & 3) * 2;
            const int r0  = row0 + wm * 64 + mt * 16 + (lane >> 2);
            if (HALF_OUT) {
                __half* C = (__half*)Cv;
                *(__half2*)(C + (size_t)r0 * N + col)       = __floats2half2_rn(acc[mt][nt][0], acc[mt][nt][1]);
                *(__half2*)(C + (size_t)(r0 + 8) * N + col) = __floats2half2_rn(acc[mt][nt][2], acc[mt][nt][3]);
            } else {
                float* C = (float*)Cv;
                *(float2*)(C + (size_t)r0 * N + col)       = make_float2(acc[mt][nt][0], acc[mt][nt][1]);
                *(float2*)(C + (size_t)(r0 + 8) * N + col) = make_float2(acc[mt][nt][2], acc[mt][nt][3]);
            }
        }
    }
}

// ---------------------------------------------------------------------------
// Flash attention (round-10 form, frozen): 128 q rows/block, 4 warps,
// unnormalized base-2 softmax, exp2 interleaved with PV at ks granularity.
// ---------------------------------------------------------------------------
#define FQ        16384
#define FSTG      16384
#define FLASH_SMEM (FQ + 2 * FSTG)
#define SCALE2    0.18033688f        // 0.125 * log2(e)

__global__ __launch_bounds__(128, 2)
void flash_h(const __half* __restrict__ qkv, __half* __restrict__ attnh)
{
    extern __shared__ char smem[];
    const uint32_t sb = smem_u32(smem);
    const int tid = threadIdx.x, lane = tid & 31, wq = tid >> 5;
    const int b = blockIdx.z, h = blockIdx.y;
    const int qi  = gridDim.x - 1 - blockIdx.x;
    const int kvh = h & (NKVH - 1);
    const int q0  = qi * 128;

#pragma unroll
    for (int t = 0; t < 8; t++) {
        int idx = tid + t * 128;
        int r = idx >> 3, cc = idx & 7;
        uint4 v = *(const uint4*)(qkv + (size_t)(b * SEQ + q0 + r) * QKVROW + h * HD + cc * 8);
        *(uint4*)(smem + SWZ128((uint32_t)(r * 128 + cc * 16))) = v;
    }

    auto load_kv = [&](int s, int kt) {
        const int k0 = kt * 64;
        const uint32_t sK = sb + FQ + s * FSTG, sV = sK + 8192;
#pragma unroll
        for (int t = 0; t < 4; t++) {
            int idx = tid + t * 128;
            int r = idx >> 3, cc = idx & 7;
            uint32_t off = SWZ128((uint32_t)(r * 128 + cc * 16));
            const __half* base = qkv + (size_t)(b * SEQ + k0 + r) * QKVROW;
            cp16(sK + off, base + (NHEADS + kvh) * HD + cc * 8);
            cp16(sV + off, base + (NHEADS + NKVH + kvh) * HD + cc * 8);
        }
        cp_commit();
    };

    float l_s[4] = { 0.f, 0.f, 0.f, 0.f };
    float oacc[2][8][4];
#pragma unroll
    for (int mt = 0; mt < 2; mt++)
#pragma unroll
        for (int j = 0; j < 8; j++)
#pragma unroll
            for (int c = 0; c < 4; c++) oacc[mt][j][c] = 0.f;

    const int ktmax = 2 * qi + 1;
    load_kv(0, 0);

    for (int kt = 0; kt <= ktmax; kt++) {
        cp_wait<0>();
        __syncthreads();
        if (kt < ktmax) load_kv((kt + 1) & 1, kt + 1);

        const uint32_t sK = sb + FQ + (kt & 1) * FSTG, sV = sK + 8192;

        float sacc[2][8][4];
#pragma unroll
        for (int mt = 0; mt < 2; mt++)
#pragma unroll
            for (int j = 0; j < 8; j++)
#pragma unroll
                for (int c = 0; c < 4; c++) sacc[mt][j][c] = 0.f;

#pragma unroll
        for (int ks = 0; ks < 4; ks++) {
            uint32_t aq[2][4];
#pragma unroll
            for (int mt = 0; mt < 2; mt++)
                ldsm4(aq[mt], sb + SWZ128((uint32_t)((wq * 32 + mt * 16 + (lane & 15)) * 128
                                                      + (ks * 2 + (lane >> 4)) * 16)));
#pragma unroll
            for (int bt = 0; bt < 4; bt++) {
                uint32_t bf[4];
                ldsm4(bf, sK + SWZ128((uint32_t)((bt * 16 + ((lane >> 4) << 3) + (lane & 7)) * 128
                                                  + (ks * 2 + ((lane >> 3) & 1)) * 16)));
#pragma unroll
                for (int mt = 0; mt < 2; mt++) {
                    mma16816(sacc[mt][2 * bt],     aq[mt], bf);
                    mma16816(sacc[mt][2 * bt + 1], aq[mt], bf + 2);
                }
            }
        }

        const int rr0 = q0 + wq * 32 + (lane >> 2);
        const int rowv[4] = { rr0, rr0 + 8, rr0 + 16, rr0 + 24 };
        const int cbase = kt * 64 + (lane & 3) * 2;
        const bool diag = (kt * 64 + 63 > rr0);

#pragma unroll
        for (int ks = 0; ks < 4; ks++) {
            uint32_t vf[4][4];
#pragma unroll
            for (int vt = 0; vt < 4; vt++)
                ldsm4t(vf[vt], sV + SWZ128((uint32_t)((ks * 16 + ((lane >> 3) & 1) * 8 + (lane & 7)) * 128
                                                       + (2 * vt + (lane >> 4)) * 16)));

            uint32_t pp[2][4];
#pragma unroll
            for (int jj = 0; jj < 2; jj++) {
                const int j = 2 * ks + jj;
#pragma unroll
                for (int mt = 0; mt < 2; mt++) {
                    float v0 = sacc[mt][j][0] * SCALE2;
                    float v1 = sacc[mt][j][1] * SCALE2;
                    float v2 = sacc[mt][j][2] * SCALE2;
                    float v3 = sacc[mt][j][3] * SCALE2;
                    if (diag) {
                        const int c0 = cbase + j * 8, c1 = c0 + 1;
                        if (c0 > rowv[2 * mt])     v0 = -1e30f;
                        if (c1 > rowv[2 * mt])     v1 = -1e30f;
                        if (c0 > rowv[2 * mt + 1]) v2 = -1e30f;
                        if (c1 > rowv[2 * mt + 1]) v3 = -1e30f;
                    }
                    float p0 = exp2f(v0), p1 = exp2f(v1);
                    float p2 = exp2f(v2), p3 = exp2f(v3);
                    l_s[2 * mt]     += p0 + p1;
                    l_s[2 * mt + 1] += p2 + p3;
                    __half2 h01 = __floats2half2_rn(p0, p1);
                    __half2 h23 = __floats2half2_rn(p2, p3);
                    pp[mt][2 * jj]     = *(uint32_t*)&h01;
                    pp[mt][2 * jj + 1] = *(uint32_t*)&h23;
                }
            }

#pragma unroll
            for (int vt = 0; vt < 4; vt++)
#pragma unroll
                for (int mt = 0; mt < 2; mt++) {
                    uint32_t ap[4] = { pp[mt][0], pp[mt][1], pp[mt][2], pp[mt][3] };
                    mma16816(oacc[mt][2 * vt],     ap, vf[vt]);
                    mma16816(oacc[mt][2 * vt + 1], ap, vf[vt] + 2);
                }
        }
    }

#pragma unroll
    for (int i = 0; i < 4; i++) {
        l_s[i] += __shfl_xor_sync(0xffffffffu, l_s[i], 1);
        l_s[i] += __shfl_xor_sync(0xffffffffu, l_s[i], 2);
    }
#pragma unroll
    for (int mt = 0; mt < 2; mt++) {
        const int r0 = q0 + wq * 32 + mt * 16 + (lane >> 2), r1 = r0 + 8;
        const float il0 = 1.f / l_s[2 * mt], il1 = 1.f / l_s[2 * mt + 1];
#pragma unroll
        for (int j = 0; j < 8; j++) {
            const int col = h * 64 + j * 8 + (lane & 3) * 2;
            __half2 v0 = __floats2half2_rn(oacc[mt][j][0] * il0, oacc[mt][j][1] * il0);
            __half2 v1 = __floats2half2_rn(oacc[mt][j][2] * il1, oacc[mt][j][3] * il1);
            *(__half2*)(attnh + (size_t)(b * SEQ + r0) * DIM + col) = v0;
            *(__half2*)(attnh + (size_t)(b * SEQ + r1) * DIM + col) = v1;
        }
    }
}

// ---------------------------------------------------------------------------
extern "C" void kernel_launch(void* const* d_in, const int* in_sizes, int n_in,
                              void* d_out, int out_size)
{
    const float* x    = (const float*)d_in[0];
    const float* Wqkv = (const float*)d_in[1];
    const float* Wout = (const float*)d_in[2];
    float* out = (float*)d_out;

    __half *xh, *wqh, *woh, *qkvh, *atth;
    cudaGetSymbolAddress((void**)&xh,   g_xh);
    cudaGetSymbolAddress((void**)&wqh,  g_wqh);
    cudaGetSymbolAddress((void**)&woh,  g_woh);
    cudaGetSymbolAddress((void**)&qkvh, g_qkvh);
    cudaGetSymbolAddress((void**)&atth, g_atth);

    cudaFuncSetAttribute(gemm_h<false>, cudaFuncAttributeMaxDynamicSharedMemorySize, GEMM_SMEM);
    cudaFuncSetAttribute(gemm_h2<true>, cudaFuncAttributeMaxDynamicSharedMemorySize, GEMM2_SMEM);
    cudaFuncSetAttribute(flash_h, cudaFuncAttributeMaxDynamicSharedMemorySize, FLASH_SMEM);

    // 0) fp32 -> fp16, single fused launch
    to_half3<<<CONV_BLOCKS, 256>>>(x, xh, Wqkv, wqh, Wout, woh);

    // 1) qkv = x @ Wqkv^T  (fp16 out) — v2: BN=256, 4-stage, 8 warps
    {
        dim3 grid(QKVROW / 256, MROWS / 128);
        gemm_h2<true><<<grid, 256, GEMM2_SMEM>>>(xh, wqh, qkvh, MROWS, QKVROW, DIM);
    }
    // 2) causal GQA flash attention (frozen)
    {
        dim3 grid(SEQ / 128, NHEADS, BATCH);
        flash_h<<<grid, 128, FLASH_SMEM>>>(qkvh, atth);
    }
    // 3) out = attn @ Wout^T  (fp32 out) — v1, frozen
    {
        dim3 grid(DIM / 128, MROWS / 128);
        gemm_h<false><<<grid, 128, GEMM_SMEM>>>(atth, woh, out, MROWS, DIM, DIM);
    }
}

// round 12
// speedup vs baseline: 1.0499x; 1.0499x over previous
#include <cuda_runtime.h>
#include <cuda_fp16.h>
#include <cstdint>

#define BATCH   2
#define SEQ     2048
#define DIM     2048
#define NHEADS  32
#define NKVH    8
#define HD      64
#define QKVROW  3072
#define MROWS   4096

// ---------------- scratch (__device__ globals; no allocs) ------------------
__device__ __half g_xh  [(size_t)MROWS  * DIM];
__device__ __half g_wqh [(size_t)QKVROW * DIM];
__device__ __half g_woh [(size_t)DIM    * DIM];
__device__ __half g_qkvh[(size_t)MROWS  * QKVROW];
__device__ __half g_atth[(size_t)MROWS  * DIM];

// ---------------- helpers ---------------------------------------------------
__device__ __forceinline__ uint32_t smem_u32(const void* p) {
    uint32_t a;
    asm("{ .reg .u64 t; cvta.to.shared.u64 t, %1; cvt.u32.u64 %0, t; }" : "=r"(a) : "l"(p));
    return a;
}
#define SWZ128(off) ((off) ^ (((off) >> 3) & 0x70))

__device__ __forceinline__ void cp16(uint32_t dst, const void* src) {
    asm volatile("cp.async.cg.shared.global [%0], [%1], 16;" :: "r"(dst), "l"(src) : "memory");
}
__device__ __forceinline__ void cp_commit() {
    asm volatile("cp.async.commit_group;" ::: "memory");
}
template <int N>
__device__ __forceinline__ void cp_wait() {
    asm volatile("cp.async.wait_group %0;" :: "n"(N) : "memory");
}
__device__ __forceinline__ void ldsm4(uint32_t* r, uint32_t addr) {
    asm volatile("ldmatrix.sync.aligned.m8n8.x4.shared.b16 {%0,%1,%2,%3}, [%4];"
                 : "=r"(r[0]), "=r"(r[1]), "=r"(r[2]), "=r"(r[3]) : "r"(addr));
}
__device__ __forceinline__ void ldsm4t(uint32_t* r, uint32_t addr) {
    asm volatile("ldmatrix.sync.aligned.m8n8.x4.trans.shared.b16 {%0,%1,%2,%3}, [%4];"
                 : "=r"(r[0]), "=r"(r[1]), "=r"(r[2]), "=r"(r[3]) : "r"(addr));
}
__device__ __forceinline__ void mma16816(float* c, const uint32_t* a, const uint32_t* b) {
    asm volatile("mma.sync.aligned.m16n8k16.row.col.f32.f16.f16.f32 "
                 "{%0,%1,%2,%3}, {%4,%5,%6,%7}, {%8,%9}, {%0,%1,%2,%3};"
                 : "+f"(c[0]), "+f"(c[1]), "+f"(c[2]), "+f"(c[3])
                 : "r"(a[0]), "r"(a[1]), "r"(a[2]), "r"(a[3]), "r"(b[0]), "r"(b[1]));
}

// ---------------------------------------------------------------------------
// fused fp32 -> fp16 conversion for x, Wqkv, Wout in ONE launch
// ---------------------------------------------------------------------------
#define N1 (MROWS * DIM)
#define N2 (QKVROW * DIM)
#define N3 (DIM * DIM)
#define CONV_BLOCKS ((N1 + N2 + N3) / 2048)

__global__ void to_half3(const float* __restrict__ x,  __half* __restrict__ xh,
                         const float* __restrict__ wq, __half* __restrict__ wqh,
                         const float* __restrict__ wo, __half* __restrict__ woh)
{
    const float* in;
    __half* out;
    int bid = blockIdx.x;
    if (bid < N1 / 2048)            { in = x;  out = xh; }
    else if (bid < (N1 + N2) / 2048){ in = wq; out = wqh; bid -= N1 / 2048; }
    else                            { in = wo; out = woh; bid -= (N1 + N2) / 2048; }

    int i = (bid * 256 + threadIdx.x) * 8;
    float4 a = *(const float4*)(in + i);
    float4 b = *(const float4*)(in + i + 4);
    __half2* o = (__half2*)(out + i);
    o[0] = __floats2half2_rn(a.x, a.y);
    o[1] = __floats2half2_rn(a.z, a.w);
    o[2] = __floats2half2_rn(b.x, b.y);
    o[3] = __floats2half2_rn(b.z, b.w);
}

// ---------------------------------------------------------------------------
// HMMA GEMM (round-7 form, frozen): BM=BN=128, BK=64, 4 warps 64x64,
// 3 stages, one sync/iter, 2 blocks/SM.
// ---------------------------------------------------------------------------
#define GBK   64
#define ASZ   (128 * 128)
#define GSTG_B (2 * ASZ)
#define GEMM_SMEM (3 * GSTG_B)

template<bool HALF_OUT>
__global__ __launch_bounds__(128, 2)
void gemm_h(const __half* __restrict__ A, const __half* __restrict__ B,
            void* __restrict__ Cv, int M, int N, int K)
{
    extern __shared__ char smem[];
    const uint32_t sb0 = smem_u32(smem);
    const int tid = threadIdx.x, lane = tid & 31, wid = tid >> 5;
    const int wm = wid & 1, wn = wid >> 1;
    const int row0 = blockIdx.y * 128, col0 = blockIdx.x * 128;
    const int NITER = K / GBK;

    auto load_stage = [&](int s, int c) {
        const int k0 = c * GBK;
        const uint32_t sA = sb0 + s * GSTG_B, sB = sA + ASZ;
#pragma unroll
        for (int t = 0; t < 8; t++) {
            int idx = tid + t * 128;
            int r = idx >> 3, cc = idx & 7;
            uint32_t off = SWZ128((uint32_t)(r * 128 + cc * 16));
            cp16(sA + off, A + (size_t)(row0 + r) * K + k0 + cc * 8);
            cp16(sB + off, B + (size_t)(col0 + r) * K + k0 + cc * 8);
        }
        cp_commit();
    };

    float acc[4][8][4];
#pragma unroll
    for (int a = 0; a < 4; a++)
#pragma unroll
        for (int b = 0; b < 8; b++)
#pragma unroll
            for (int c = 0; c < 4; c++) acc[a][b][c] = 0.f;

    load_stage(0, 0);
    load_stage(1, 1);

    for (int i = 0; i < NITER; i++) {
        if (i + 1 < NITER) cp_wait<1>(); else cp_wait<0>();
        __syncthreads();
        if (i + 2 < NITER) load_stage((i + 2) % 3, i + 2);

        const uint32_t sA = sb0 + (i % 3) * GSTG_B, sB = sA + ASZ;
#pragma unroll
        for (int ks = 0; ks < 4; ks++) {
            uint32_t af[4][4];
#pragma unroll
            for (int mt = 0; mt < 4; mt++)
                ldsm4(af[mt], sA + SWZ128((uint32_t)((wm * 64 + mt * 16 + (lane & 15)) * 128
                                                      + (ks * 2 + (lane >> 4)) * 16)));
#pragma unroll
            for (int bt = 0; bt < 4; bt++) {
                uint32_t bf[4];
                ldsm4(bf, sB + SWZ128((uint32_t)((wn * 64 + bt * 16 + ((lane >> 4) << 3) + (lane & 7)) * 128
                                                  + (ks * 2 + ((lane >> 3) & 1)) * 16)));
#pragma unroll
                for (int mt = 0; mt < 4; mt++) {
                    mma16816(acc[mt][2 * bt],     af[mt], bf);
                    mma16816(acc[mt][2 * bt + 1], af[mt], bf + 2);
                }
            }
        }
    }

#pragma unroll
    for (int mt = 0; mt < 4; mt++) {
#pragma unroll
        for (int nt = 0; nt < 8; nt++) {
            const int col = col0 + wn * 64 + nt * 8 + (lane & 3) * 2;
            const int r0  = row0 + wm * 64 + mt * 16 + (lane >> 2);
            if (HALF_OUT) {
                __half* C = (__half*)Cv;
                *(__half2*)(C + (size_t)r0 * N + col)       = __floats2half2_rn(acc[mt][nt][0], acc[mt][nt][1]);
                *(__half2*)(C + (size_t)(r0 + 8) * N + col) = __floats2half2_rn(acc[mt][nt][2], acc[mt][nt][3]);
            } else {
                float* C = (float*)Cv;
                *(float2*)(C + (size_t)r0 * N + col)       = make_float2(acc[mt][nt][0], acc[mt][nt][1]);
                *(float2*)(C + (size_t)(r0 + 8) * N + col) = make_float2(acc[mt][nt][2], acc[mt][nt][3]);
            }
        }
    }
}

// ---------------------------------------------------------------------------
// Flash attention: 128 q rows/block, 4 warps (32x64 warp tile).
// Unnormalized base-2 softmax, exp2 interleaved with PV at ks granularity.
// NEW: Q fragments cached in registers across the whole kv loop (8 LDSM per
// block instead of per tile), and fully-masked warp-tiles skipped exactly.
// smem: Q[16K] + 2 stages x (K[8K]+V[8K]) = 49152 B, 2 blocks/SM.
// ---------------------------------------------------------------------------
#define FQ        16384
#define FSTG      16384
#define FLASH_SMEM (FQ + 2 * FSTG)
#define SCALE2    0.18033688f        // 0.125 * log2(e)

__global__ __launch_bounds__(128, 2)
void flash_h(const __half* __restrict__ qkv, __half* __restrict__ attnh)
{
    extern __shared__ char smem[];
    const uint32_t sb = smem_u32(smem);
    const int tid = threadIdx.x, lane = tid & 31, wq = tid >> 5;
    const int b = blockIdx.z, h = blockIdx.y;
    const int qi  = gridDim.x - 1 - blockIdx.x;     // heavy tiles first
    const int kvh = h & (NKVH - 1);
    const int q0  = qi * 128;

    auto load_kv = [&](int s, int kt) {
        const int k0 = kt * 64;
        const uint32_t sK = sb + FQ + s * FSTG, sV = sK + 8192;
#pragma unroll
        for (int t = 0; t < 4; t++) {
            int idx = tid + t * 128;
            int r = idx >> 3, cc = idx & 7;
            uint32_t off = SWZ128((uint32_t)(r * 128 + cc * 16));
            const __half* base = qkv + (size_t)(b * SEQ + k0 + r) * QKVROW;
            cp16(sK + off, base + (NHEADS + kvh) * HD + cc * 8);
            cp16(sV + off, base + (NHEADS + NKVH + kvh) * HD + cc * 8);
        }
        cp_commit();
    };

    // prefetch KV tile 0 first, then stage Q
    load_kv(0, 0);

#pragma unroll
    for (int t = 0; t < 8; t++) {
        int idx = tid + t * 128;
        int r = idx >> 3, cc = idx & 7;
        uint4 v = *(const uint4*)(qkv + (size_t)(b * SEQ + q0 + r) * QKVROW + h * HD + cc * 8);
        *(uint4*)(smem + SWZ128((uint32_t)(r * 128 + cc * 16))) = v;
    }
    __syncthreads();

    // cache Q fragments for the entire kv loop (8 ldsm, once)
    uint32_t aqc[4][2][4];
#pragma unroll
    for (int ks = 0; ks < 4; ks++)
#pragma unroll
        for (int mt = 0; mt < 2; mt++)
            ldsm4(aqc[ks][mt], sb + SWZ128((uint32_t)((wq * 32 + mt * 16 + (lane & 15)) * 128
                                                       + (ks * 2 + (lane >> 4)) * 16)));

    float l_s[4] = { 0.f, 0.f, 0.f, 0.f };
    float oacc[2][8][4];
#pragma unroll
    for (int mt = 0; mt < 2; mt++)
#pragma unroll
        for (int j = 0; j < 8; j++)
#pragma unroll
            for (int c = 0; c < 4; c++) oacc[mt][j][c] = 0.f;

    const int ktmax = 2 * qi + 1;
    const int rowmax = q0 + wq * 32 + 31;     // last row this warp owns

    for (int kt = 0; kt <= ktmax; kt++) {
        cp_wait<0>();
        __syncthreads();
        if (kt < ktmax) load_kv((kt + 1) & 1, kt + 1);

        // fully-masked warp-tile: contributes exactly zero — skip compute
        if (kt * 64 > rowmax) continue;

        const uint32_t sK = sb + FQ + (kt & 1) * FSTG, sV = sK + 8192;

        // ---- S = Q @ K^T (warp 32x64, k=64), Q from register cache ----
        float sacc[2][8][4];
#pragma unroll
        for (int mt = 0; mt < 2; mt++)
#pragma unroll
            for (int j = 0; j < 8; j++)
#pragma unroll
                for (int c = 0; c < 4; c++) sacc[mt][j][c] = 0.f;

#pragma unroll
        for (int ks = 0; ks < 4; ks++) {
#pragma unroll
            for (int bt = 0; bt < 4; bt++) {
                uint32_t bf[4];
                ldsm4(bf, sK + SWZ128((uint32_t)((bt * 16 + ((lane >> 4) << 3) + (lane & 7)) * 128
                                                  + (ks * 2 + ((lane >> 3) & 1)) * 16)));
#pragma unroll
                for (int mt = 0; mt < 2; mt++) {
                    mma16816(sacc[mt][2 * bt],     aqc[ks][mt], bf);
                    mma16816(sacc[mt][2 * bt + 1], aqc[ks][mt], bf + 2);
                }
            }
        }

        // ---- interleaved: per ks chunk, V ldsm -> exp/pack -> PV MMAs ----
        const int rr0 = q0 + wq * 32 + (lane >> 2);
        const int rowv[4] = { rr0, rr0 + 8, rr0 + 16, rr0 + 24 };
        const int cbase = kt * 64 + (lane & 3) * 2;
        const bool diag = (kt * 64 + 63 > rr0);

#pragma unroll
        for (int ks = 0; ks < 4; ks++) {
            uint32_t vf[4][4];
#pragma unroll
            for (int vt = 0; vt < 4; vt++)
                ldsm4t(vf[vt], sV + SWZ128((uint32_t)((ks * 16 + ((lane >> 3) & 1) * 8 + (lane & 7)) * 128
                                                       + (2 * vt + (lane >> 4)) * 16)));

            uint32_t pp[2][4];
#pragma unroll
            for (int jj = 0; jj < 2; jj++) {
                const int j = 2 * ks + jj;
#pragma unroll
                for (int mt = 0; mt < 2; mt++) {
                    float v0 = sacc[mt][j][0] * SCALE2;
                    float v1 = sacc[mt][j][1] * SCALE2;
                    float v2 = sacc[mt][j][2] * SCALE2;
                    float v3 = sacc[mt][j][3] * SCALE2;
                    if (diag) {
                        const int c0 = cbase + j * 8, c1 = c0 + 1;
                        if (c0 > rowv[2 * mt])     v0 = -1e30f;
                        if (c1 > rowv[2 * mt])     v1 = -1e30f;
                        if (c0 > rowv[2 * mt + 1]) v2 = -1e30f;
                        if (c1 > rowv[2 * mt + 1]) v3 = -1e30f;
                    }
                    float p0 = exp2f(v0), p1 = exp2f(v1);
                    float p2 = exp2f(v2), p3 = exp2f(v3);
                    l_s[2 * mt]     += p0 + p1;
                    l_s[2 * mt + 1] += p2 + p3;
                    __half2 h01 = __floats2half2_rn(p0, p1);
                    __half2 h23 = __floats2half2_rn(p2, p3);
                    pp[mt][2 * jj]     = *(uint32_t*)&h01;
                    pp[mt][2 * jj + 1] = *(uint32_t*)&h23;
                }
            }

#pragma unroll
            for (int vt = 0; vt < 4; vt++)
#pragma unroll
                for (int mt = 0; mt < 2; mt++) {
                    uint32_t ap[4] = { pp[mt][0], pp[mt][1], pp[mt][2], pp[mt][3] };
                    mma16816(oacc[mt][2 * vt],     ap, vf[vt]);
                    mma16816(oacc[mt][2 * vt + 1], ap, vf[vt] + 2);
                }
        }
    }

    // epilogue: reduce l across the 4 lanes of each row, normalize, store
#pragma unroll
    for (int i = 0; i < 4; i++) {
        l_s[i] += __shfl_xor_sync(0xffffffffu, l_s[i], 1);
        l_s[i] += __shfl_xor_sync(0xffffffffu, l_s[i], 2);
    }
#pragma unroll
    for (int mt = 0; mt < 2; mt++) {
        const int r0 = q0 + wq * 32 + mt * 16 + (lane >> 2), r1 = r0 + 8;
        const float il0 = 1.f / l_s[2 * mt], il1 = 1.f / l_s[2 * mt + 1];
#pragma unroll
        for (int j = 0; j < 8; j++) {
            const int col = h * 64 + j * 8 + (lane & 3) * 2;
            __half2 v0 = __floats2half2_rn(oacc[mt][j][0] * il0, oacc[mt][j][1] * il0);
            __half2 v1 = __floats2half2_rn(oacc[mt][j][2] * il1, oacc[mt][j][3] * il1);
            *(__half2*)(attnh + (size_t)(b * SEQ + r0) * DIM + col) = v0;
            *(__half2*)(attnh + (size_t)(b * SEQ + r1) * DIM + col) = v1;
        }
    }
}

// ---------------------------------------------------------------------------
extern "C" void kernel_launch(void* const* d_in, const int* in_sizes, int n_in,
                              void* d_out, int out_size)
{
    const float* x    = (const float*)d_in[0];
    const float* Wqkv = (const float*)d_in[1];
    const float* Wout = (const float*)d_in[2];
    float* out = (float*)d_out;

    __half *xh, *wqh, *woh, *qkvh, *atth;
    cudaGetSymbolAddress((void**)&xh,   g_xh);
    cudaGetSymbolAddress((void**)&wqh,  g_wqh);
    cudaGetSymbolAddress((void**)&woh,  g_woh);
    cudaGetSymbolAddress((void**)&qkvh, g_qkvh);
    cudaGetSymbolAddress((void**)&atth, g_atth);

    cudaFuncSetAttribute(gemm_h<true>,  cudaFuncAttributeMaxDynamicSharedMemorySize, GEMM_SMEM);
    cudaFuncSetAttribute(gemm_h<false>, cudaFuncAttributeMaxDynamicSharedMemorySize, GEMM_SMEM);
    cudaFuncSetAttribute(flash_h, cudaFuncAttributeMaxDynamicSharedMemorySize, FLASH_SMEM);

    // 0) fp32 -> fp16, single fused launch
    to_half3<<<CONV_BLOCKS, 256>>>(x, xh, Wqkv, wqh, Wout, woh);

    // 1) qkv = x @ Wqkv^T  (fp16 out) — v1, known best
    {
        dim3 grid(QKVROW / 128, MROWS / 128);
        gemm_h<true><<<grid, 128, GEMM_SMEM>>>(xh, wqh, qkvh, MROWS, QKVROW, DIM);
    }
    // 2) causal GQA flash attention (Q-frag cache + masked-tile skip)
    {
        dim3 grid(SEQ / 128, NHEADS, BATCH);
        flash_h<<<grid, 128, FLASH_SMEM>>>(qkvh, atth);
    }
    // 3) out = attn @ Wout^T  (fp32 out) — v1, frozen
    {
        dim3 grid(DIM / 128, MROWS / 128);
        gemm_h<false><<<grid, 128, GEMM_SMEM>>>(atth, woh, out, MROWS, DIM, DIM);
    }
}